// round 4
// baseline (speedup 1.0000x reference)
#include <cuda_runtime.h>
#include <cuda_bf16.h>

// CovarianceResidualError, fully fused single persistent kernel:
//   a_i = graph_emb[i,0];  ACC_j = sum_i e_ij*a_i;  SE_j = sum_i e_ij;  SA = sum_i a_i
//   out = -sum_j |ACC_j - SA*SE_j/N|
//
// Phase 1: 512 blocks x 256 threads compute per-block partials (deterministic).
// Grid barrier via counter (all 512 CTAs resident: 148 SMs x occupancy 4 = 592).
// Phase 2: blocks 0..31 reduce columns from L2-warm partials; last-arriving
//          block (ticket) does SA + deterministic final |.| sum.

#define NROWS 131072
#define OCOLS 256
#define DCOLS 128
#define NB 512
#define ROWS_PER_BLK (NROWS / NB)          // 256
#define CHUNK 64
#define NCHUNK (ROWS_PER_BLK / CHUNK)      // 4
#define NRED 32                            // reducer blocks (8 columns each)

__device__ float g_pacc[NB * OCOLS];
__device__ float g_pse [NB * OCOLS];
__device__ float g_psa [NB];
__device__ float g_colA[OCOLS];
__device__ float g_colS[OCOLS];
__device__ volatile unsigned int g_c1 = 0;   // phase-1 completion counter
__device__ unsigned int g_c2 = 0;            // reducer ticket

__global__ void __launch_bounds__(256, 4)
cov_fused_kernel(const float* __restrict__ ge, const float4* __restrict__ err4,
                 float* __restrict__ out)
{
    __shared__ float a_sh[CHUNK];
    __shared__ float red[4 * OCOLS];
    __shared__ float shA[NRED][8];
    __shared__ float shS[NRED][8];
    __shared__ unsigned int s_ticket;

    const int tid  = threadIdx.x;
    const int tx   = tid & 63;     // column group: columns 4*tx .. 4*tx+3
    const int ty   = tid >> 6;     // row phase 0..3
    const int row0 = blockIdx.x * ROWS_PER_BLK;

    // ================= Phase 1: per-block partials =================
    float4 acc = make_float4(0.f, 0.f, 0.f, 0.f);
    float4 se  = make_float4(0.f, 0.f, 0.f, 0.f);
    float  suma = 0.f;

    float a_next = 0.f;
    if (tid < CHUNK)
        a_next = ge[(size_t)(row0 + tid) * DCOLS];

    for (int c = 0; c < NCHUNK; ++c) {
        const int base = row0 + c * CHUNK;
        __syncthreads();
        if (tid < CHUNK) { a_sh[tid] = a_next; suma += a_next; }
        __syncthreads();
        if (tid < CHUNK && (c + 1) < NCHUNK)
            a_next = ge[(size_t)(base + CHUNK + tid) * DCOLS];

        #pragma unroll
        for (int r = ty; r < CHUNK; r += 4) {
            const float4 e = err4[(size_t)(base + r) * (OCOLS / 4) + tx];
            const float  a = a_sh[r];
            acc.x = fmaf(e.x, a, acc.x); acc.y = fmaf(e.y, a, acc.y);
            acc.z = fmaf(e.z, a, acc.z); acc.w = fmaf(e.w, a, acc.w);
            se.x += e.x; se.y += e.y; se.z += e.z; se.w += e.w;
        }
    }

    __syncthreads();
    red[ty * OCOLS + 4 * tx + 0] = acc.x;
    red[ty * OCOLS + 4 * tx + 1] = acc.y;
    red[ty * OCOLS + 4 * tx + 2] = acc.z;
    red[ty * OCOLS + 4 * tx + 3] = acc.w;
    __syncthreads();
    g_pacc[blockIdx.x * OCOLS + tid] =
        red[tid] + red[OCOLS + tid] + red[2 * OCOLS + tid] + red[3 * OCOLS + tid];
    __syncthreads();
    red[ty * OCOLS + 4 * tx + 0] = se.x;
    red[ty * OCOLS + 4 * tx + 1] = se.y;
    red[ty * OCOLS + 4 * tx + 2] = se.z;
    red[ty * OCOLS + 4 * tx + 3] = se.w;
    __syncthreads();
    g_pse[blockIdx.x * OCOLS + tid] =
        red[tid] + red[OCOLS + tid] + red[2 * OCOLS + tid] + red[3 * OCOLS + tid];

    __syncthreads();
    if (tid < CHUNK) red[tid] = suma;
    __syncthreads();
    if (tid == 0) {
        float s = 0.f;
        #pragma unroll
        for (int i = 0; i < CHUNK; ++i) s += red[i];
        g_psa[blockIdx.x] = s;
        __threadfence();
        atomicAdd((unsigned int*)&g_c1, 1u);
    }

    if (blockIdx.x >= NRED) return;

    // ================= grid barrier (spin; all CTAs resident) =================
    if (tid == 0) {
        while (g_c1 != NB) { /* spin */ }
    }
    __syncthreads();
    __threadfence();

    // ================= Phase 2: coalesced column reduce =================
    const int cc = tid & 7;        // column within this block's group of 8
    const int r  = tid >> 3;       // 0..31 partial-row lane
    const int c  = blockIdx.x * 8 + cc;

    float a = 0.f, s = 0.f;
    #pragma unroll
    for (int k = 0; k < NB / 32; ++k) {        // 16 steps, L2-warm
        const int row = r + k * 32;
        a += g_pacc[(size_t)row * OCOLS + c];
        s += g_pse [(size_t)row * OCOLS + c];
    }
    shA[r][cc] = a;
    shS[r][cc] = s;
    __syncthreads();
    #pragma unroll
    for (int st = 16; st > 0; st >>= 1) {
        if (r < st) {
            shA[r][cc] += shA[r + st][cc];
            shS[r][cc] += shS[r + st][cc];
        }
        __syncthreads();
    }
    if (r == 0) {
        g_colA[c] = shA[0][cc];
        g_colS[c] = shS[0][cc];
    }

    if (tid == 0) {
        __threadfence();
        s_ticket = atomicAdd(&g_c2, 1u);
    }
    __syncthreads();

    // ================= Phase 3: last reducer does final scalar =================
    if (s_ticket == NRED - 1) {
        __threadfence();
        // SA over 512 block partials (fixed-shape tree in 'red')
        red[tid] = g_psa[tid] + g_psa[tid + 256];
        __syncthreads();
        #pragma unroll
        for (int st = 128; st > 0; st >>= 1) {
            if (tid < st) red[tid] += red[tid + st];
            __syncthreads();
        }
        const float k = red[0] * (1.0f / (float)NROWS);
        __syncthreads();

        red[tid] = fabsf(g_colA[tid] - k * g_colS[tid]);
        __syncthreads();
        #pragma unroll
        for (int st = 128; st > 0; st >>= 1) {
            if (tid < st) red[tid] += red[tid + st];
            __syncthreads();
        }
        if (tid == 0) {
            out[0] = -red[0];
            g_c2 = 0;                         // reset for next graph replay
            *(unsigned int*)&g_c1 = 0;
            __threadfence();
        }
    }
}

extern "C" void kernel_launch(void* const* d_in, const int* in_sizes, int n_in,
                              void* d_out, int out_size)
{
    const float* ge  = nullptr;   // graph_emb (N x 128)
    const float* err = nullptr;   // errors    (N x 256)
    for (int i = 0; i < n_in; ++i) {
        if (in_sizes[i] == NROWS * DCOLS) ge  = (const float*)d_in[i];
        else if (in_sizes[i] == NROWS * OCOLS) err = (const float*)d_in[i];
    }

    cov_fused_kernel<<<NB, 256>>>(ge, (const float4*)err, (float*)d_out);
}